// round 15
// baseline (speedup 1.0000x reference)
#include <cuda_runtime.h>
#include <cuda_fp16.h>
#include <math.h>
#include <stdint.h>

// ---------------------------------------------------------------- constants
#define NROWS   9216      // B*R
#define K1      2816      // IMG+TAG
#define K2      3072      // padded (3016 -> 3072)
#define K2RAW   3016
#define N1      200       // POS_EMBED
#define N1P     256       // padded
#define N2      1024
#define BOXL    15
#define PEMB    200

#define BK      64        // fp16 K elements per stage (128B per row)

// ---------------------------------------------------------------- scratch
__device__ __half g_Xf[(long)NROWS * K2];
__device__ __half g_W2f[(long)N2 * K2];
__device__ __half g_W1f[(long)N1P * K1];
__device__ float g_region[(long)NROWS * N1];

// ---------------------------------------------------------------- utils
__device__ __forceinline__ uint32_t smem_u32(const void* p) {
    uint32_t a;
    asm("{ .reg .u64 t; cvta.to.shared.u64 t, %1; cvt.u32.u64 %0, t; }"
        : "=r"(a) : "l"(p));
    return a;
}
// SW128 swizzle on 128B rows: chunk(16B) ^= row&7 — conflict-free ldsm/STS
__device__ __forceinline__ uint32_t swz128(uint32_t row, uint32_t chunk) {
    return row * 128 + ((chunk ^ (row & 7)) << 4);
}
__device__ __forceinline__ void cp16(uint32_t dst, const void* src) {
    asm volatile("cp.async.cg.shared.global [%0], [%1], 16;" :: "r"(dst), "l"(src));
}
__device__ __forceinline__ void cp_commit() {
    asm volatile("cp.async.commit_group;" ::: "memory");
}
template<int N>
__device__ __forceinline__ void cp_wait() {
    asm volatile("cp.async.wait_group %0;" :: "n"(N) : "memory");
}
__device__ __forceinline__ void ldsm4(uint32_t* r, uint32_t addr) {
    asm volatile("ldmatrix.sync.aligned.m8n8.x4.shared.b16 {%0,%1,%2,%3}, [%4];"
                 : "=r"(r[0]), "=r"(r[1]), "=r"(r[2]), "=r"(r[3]) : "r"(addr));
}
__device__ __forceinline__ void mma16816(float* d, const uint32_t* a,
                                         uint32_t b0, uint32_t b1) {
    asm volatile(
        "mma.sync.aligned.m16n8k16.row.col.f32.f16.f16.f32 "
        "{%0,%1,%2,%3}, {%4,%5,%6,%7}, {%8,%9}, {%0,%1,%2,%3};"
        : "+f"(d[0]), "+f"(d[1]), "+f"(d[2]), "+f"(d[3])
        : "r"(a[0]), "r"(a[1]), "r"(a[2]), "r"(a[3]), "r"(b0), "r"(b1));
}

// ---------------------------------------------------------------- conversions
__global__ void convX_kernel(const float* __restrict__ images,
                             const float* __restrict__ tag) {
    int i = blockIdx.x * blockDim.x + threadIdx.x;
    if (i >= NROWS * 768) return;
    int row = i / 768;
    int c4  = i - row * 768;
    float4 v;
    if (c4 < 512)      v = reinterpret_cast<const float4*>(images)[(long)row * 512 + c4];
    else if (c4 < 704) v = reinterpret_cast<const float4*>(tag)[(long)row * 192 + (c4 - 512)];
    else if (c4 < 754) return;   // box_feat region: written by attn kernel
    else               v = make_float4(0.f, 0.f, 0.f, 0.f);
    __half h[4];
    h[0] = __float2half_rn(v.x); h[1] = __float2half_rn(v.y);
    h[2] = __float2half_rn(v.z); h[3] = __float2half_rn(v.w);
    *reinterpret_cast<uint2*>(g_Xf + (long)row * K2 + c4 * 4) =
        *reinterpret_cast<uint2*>(h);
}

__global__ void convW2_kernel(const float* __restrict__ fcW) {
    int i = blockIdx.x * blockDim.x + threadIdx.x;
    if (i >= N2 * K2) return;
    int n = i / K2;
    int k = i - n * K2;
    float v;
    if (k < 2048)      v = fcW[(long)n * K2RAW + k];
    else if (k < 2816) v = fcW[(long)n * K2RAW + k + 200];
    else if (k < 3016) v = fcW[(long)n * K2RAW + k - 768];
    else               v = 0.f;
    g_W2f[i] = __float2half_rn(v);
}

__global__ void convW1_kernel(const float* __restrict__ aW) {
    int i = blockIdx.x * blockDim.x + threadIdx.x;
    if (i >= N1P * K1) return;
    int n = i / K1;
    int k = i - n * K1;
    float v = (n < N1) ? aW[(long)n * K1 + k] : 0.f;
    g_W1f[i] = __float2half_rn(v);
}

// ---------------------------------------------------------------- HMMA GEMM (fp16, f32 acc)
// C[M,N] = A[M,K]*B[N,K]^T (+bias). TBM x TBN tile per CTA, MW x NW warp grid,
// NTH threads, NSTG stages, BK=64, SW128-swizzled 128B rows,
// single barrier per K-stage, OCC CTAs/SM. NSKIP: skip padded-N column groups.
template<int TBM, int TBN, int MW, int NW, int NSTG, int NTH, int OCC, bool NSKIP>
__global__ void __launch_bounds__(NTH, OCC)
hmma_gemm(const __half* __restrict__ A, int lda,
          const __half* __restrict__ B, int ldb,
          int K, const float* __restrict__ bias,
          float* __restrict__ C, int N, int ldc) {
    constexpr int MT = (TBM / MW) / 16;
    constexpr int NT = (TBN / NW) / 8;
    constexpr int NP = NT / 2;
    constexpr int T_B = TBM * 128;
    constexpr int STAGE_B = (TBM + TBN) * 128;
    constexpr int GR_A = TBM * 8;
    constexpr int GR_TOT = (TBM + TBN) * 8;
    constexpr int LREP = GR_TOT / NTH;

    extern __shared__ char smem[];
    const uint32_t sb = smem_u32(smem);
    const int tid  = threadIdx.x;
    const int lane = tid & 31;
    const int wid  = tid >> 5;
    const int wm   = (wid % MW) * (TBM / MW);
    const int wn   = (wid / MW) * (TBN / NW);
    const long m0  = (long)blockIdx.y * TBM;
    const long n0  = (long)blockIdx.x * TBN;

    bool np_act[NP];
#pragma unroll
    for (int np = 0; np < NP; np++)
        np_act[np] = NSKIP ? (((int)n0 + wn + np * 16) < N) : true;

    float acc[MT][NT][4];
#pragma unroll
    for (int i = 0; i < MT; i++)
#pragma unroll
        for (int j = 0; j < NT; j++)
#pragma unroll
            for (int c = 0; c < 4; c++) acc[i][j][c] = 0.f;

    uint32_t a_rb[MT], a_rx[MT];
#pragma unroll
    for (int mt = 0; mt < MT; mt++) {
        uint32_t r = wm + mt * 16 + (lane & 15);
        a_rb[mt] = r * 128; a_rx[mt] = r & 7;
    }
    const uint32_t a_cb = lane >> 4;
    uint32_t b_rb[NP], b_rx[NP];
#pragma unroll
    for (int np = 0; np < NP; np++) {
        uint32_t r = wn + np * 16 + ((lane & 7) | ((lane >> 4) << 3));
        b_rb[np] = r * 128; b_rx[np] = r & 7;
    }
    const uint32_t b_cb = (lane >> 3) & 1;

    auto load_stage = [&](int buf, long kel) {
        uint32_t st = sb + buf * STAGE_B;
#pragma unroll
        for (int i = 0; i < LREP; i++) {
            int g = tid + i * NTH;
            int chunk = g & 7;
            if (g < GR_A) {
                int row = g >> 3;
                cp16(st + swz128(row, chunk),
                     A + (m0 + row) * lda + kel + chunk * 8);
            } else {
                int row = (g - GR_A) >> 3;
                cp16(st + T_B + swz128(row, chunk),
                     B + (n0 + row) * ldb + kel + chunk * 8);
            }
        }
    };

    const int S = K / BK;
#pragma unroll 1
    for (int p = 0; p < NSTG - 1; p++) {
        load_stage(p, (long)p * BK);
        cp_commit();
    }

#pragma unroll 1
    for (int s = 0; s < S; s++) {
        cp_wait<NSTG - 2>();
        __syncthreads();
        if (s + NSTG - 1 < S)
            load_stage((s + NSTG - 1) % NSTG, (long)(s + NSTG - 1) * BK);
        cp_commit();

        uint32_t st = sb + (s % NSTG) * STAGE_B;
#pragma unroll
        for (int kk = 0; kk < 4; kk++) {
            uint32_t af[MT][4], bf[NP][4];
            const uint32_t ac = kk * 2 + a_cb;
            const uint32_t bc = kk * 2 + b_cb;
#pragma unroll
            for (int mt = 0; mt < MT; mt++)
                ldsm4(af[mt], st + a_rb[mt] + ((ac ^ a_rx[mt]) << 4));
#pragma unroll
            for (int np = 0; np < NP; np++)
                if (np_act[np])
                    ldsm4(bf[np], st + T_B + b_rb[np] + ((bc ^ b_rx[np]) << 4));
#pragma unroll
            for (int np = 0; np < NP; np++)
                if (np_act[np])
#pragma unroll
                    for (int j = 0; j < 2; j++)
#pragma unroll
                        for (int mt = 0; mt < MT; mt++)
                            mma16816(acc[mt][np * 2 + j], af[mt],
                                     bf[np][2 * j], bf[np][2 * j + 1]);
        }
    }

    // epilogue
    const int gr = lane >> 2;
    const int gc = (lane & 3) * 2;
#pragma unroll
    for (int mt = 0; mt < MT; mt++) {
        long m = m0 + wm + mt * 16 + gr;
#pragma unroll
        for (int nt = 0; nt < NT; nt++) {
            int n = (int)n0 + wn + nt * 8 + gc;
            if (n < N) {
                float b0 = bias ? bias[n] : 0.f;
                float b1 = bias ? bias[n + 1] : 0.f;
                float2 v0 = make_float2(acc[mt][nt][0] + b0, acc[mt][nt][1] + b1);
                float2 v1 = make_float2(acc[mt][nt][2] + b0, acc[mt][nt][3] + b1);
                *reinterpret_cast<float2*>(C + m * ldc + n) = v0;
                *reinterpret_cast<float2*>(C + (m + 8) * ldc + n) = v1;
            }
        }
    }
}

// ---------------------------------------------------------------- attention
__global__ void attn_kernel(const float* __restrict__ boxes,
                            const float* __restrict__ pos_emb) {
    int row  = blockIdx.x * 8 + (threadIdx.x >> 5);
    int lane = threadIdx.x & 31;
    if (row >= NROWS) return;

    const float* region = g_region + (long)row * N1;
    float reg[7];
#pragma unroll
    for (int i = 0; i < 7; i++) {
        int e = lane + 32 * i;
        reg[i] = (e < PEMB) ? region[e] : 0.f;
    }

    const float* brow = boxes + (long)row * (2 * BOXL);
    int   idx[BOXL];
    float w[BOXL], sc[BOXL];
#pragma unroll
    for (int k = 0; k < BOXL; k++) {
        idx[k] = (int)brow[k];
        w[k]   = brow[BOXL + k];
    }

#pragma unroll
    for (int k = 0; k < BOXL; k++) {
        const float* pe = pos_emb + (long)idx[k] * PEMB;
        float p = 0.f;
#pragma unroll
        for (int i = 0; i < 7; i++) {
            int e = lane + 32 * i;
            if (e < PEMB) p += reg[i] * pe[e];
        }
#pragma unroll
        for (int o = 16; o > 0; o >>= 1)
            p += __shfl_xor_sync(0xffffffffu, p, o);
        sc[k] = tanhf(p);
    }

    float mx = -1e30f;
#pragma unroll
    for (int k = 0; k < BOXL; k++) mx = fmaxf(mx, sc[k]);
    float ssum = 0.f;
#pragma unroll
    for (int k = 0; k < BOXL; k++) { sc[k] = expf(sc[k] - mx); ssum += sc[k]; }
    float tot = 0.f;
#pragma unroll
    for (int k = 0; k < BOXL; k++) { sc[k] = sc[k] / ssum * w[k]; tot += sc[k]; }
    float inv = 1.f / (tot + 1e-6f);

#pragma unroll
    for (int i = 0; i < 7; i++) {
        int e = lane + 32 * i;
        if (e < PEMB) {
            float f = 0.f;
#pragma unroll
            for (int k = 0; k < BOXL; k++)
                f += sc[k] * pos_emb[(long)idx[k] * PEMB + e];
            g_Xf[(long)row * K2 + K1 + e] = __float2half_rn(f * inv);
        }
    }
}

// ---------------------------------------------------------------- L2 norm
__global__ void norm_kernel(float* __restrict__ out) {
    int row  = blockIdx.x * 8 + (threadIdx.x >> 5);
    int lane = threadIdx.x & 31;
    if (row >= NROWS) return;

    float4* p = reinterpret_cast<float4*>(out + (long)row * N2);
    float4 v[8];
    float s = 0.f;
#pragma unroll
    for (int i = 0; i < 8; i++) {
        v[i] = p[lane + 32 * i];
        s += v[i].x * v[i].x + v[i].y * v[i].y + v[i].z * v[i].z + v[i].w * v[i].w;
    }
#pragma unroll
    for (int o = 16; o > 0; o >>= 1)
        s += __shfl_xor_sync(0xffffffffu, s, o);
    float scale = 1.f / (sqrtf(s) + 1e-8f);
#pragma unroll
    for (int i = 0; i < 8; i++) {
        v[i].x *= scale; v[i].y *= scale; v[i].z *= scale; v[i].w *= scale;
        p[lane + 32 * i] = v[i];
    }
}

// ---------------------------------------------------------------- launch
#define SMEM1 (4 * (64 + 128) * 128)    //  98304 — GEMM1 (TBM=64/TBN=128, 4 stg, 2 CTA/SM)
#define SMEM2 (2 * (128 + 256) * 128)   //  98304 — GEMM2 (TBM=128/TBN=256, 2 stg, 2 CTA/SM)

extern "C" void kernel_launch(void* const* d_in, const int* in_sizes, int n_in,
                              void* d_out, int out_size) {
    const float* images  = (const float*)d_in[0];
    const float* tag     = (const float*)d_in[1];
    const float* boxes   = (const float*)d_in[2];
    const float* pos_emb = (const float*)d_in[3];
    const float* attn_W  = (const float*)d_in[4];
    const float* fc_W    = (const float*)d_in[5];
    const float* fc_b    = (const float*)d_in[6];
    float* out = (float*)d_out;

    cudaFuncSetAttribute(hmma_gemm<64, 128, 2, 2, 4, 128, 2, true>,
                         cudaFuncAttributeMaxDynamicSharedMemorySize, SMEM1);
    cudaFuncSetAttribute(hmma_gemm<128, 256, 2, 4, 2, 256, 2, false>,
                         cudaFuncAttributeMaxDynamicSharedMemorySize, SMEM2);

    void *xf, *w2f, *w1f, *rg;
    cudaGetSymbolAddress(&xf, g_Xf);
    cudaGetSymbolAddress(&w2f, g_W2f);
    cudaGetSymbolAddress(&w1f, g_W1f);
    cudaGetSymbolAddress(&rg, g_region);

    // 1. conversions (fp16)
    convX_kernel<<<(NROWS * 768 + 255) / 256, 256>>>(images, tag);
    convW2_kernel<<<(N2 * K2 + 255) / 256, 256>>>(fc_W);
    convW1_kernel<<<(N1P * K1 + 255) / 256, 256>>>(attn_W);

    // 2. GEMM1: region = X[:, :2816] @ attn_W^T
    //    288 CTAs, TBM=64, 2 CTA/SM, N-skip on padded cols (R13 best: 39.9us)
    {
        dim3 grid(N1P / 128, NROWS / 64);
        hmma_gemm<64, 128, 2, 2, 4, 128, 2, true><<<grid, 128, SMEM1>>>(
            (const __half*)xf, K2, (const __half*)w1f, K1,
            K1, nullptr, (float*)rg, N1, N1);
    }

    // 3. attention -> box_feat (fp16) into X[:, 2816:3016]
    attn_kernel<<<NROWS / 8, 256>>>(boxes, pos_emb);

    // 4. GEMM2: out = X @ W2^T + fc_b
    //    288 CTAs, TBM=128/TBN=256 (2.7x less L2 traffic), 2 CTA/SM
    {
        dim3 grid(N2 / 256, NROWS / 128);
        hmma_gemm<128, 256, 2, 4, 2, 256, 2, false><<<grid, 256, SMEM2>>>(
            (const __half*)xf, K2, (const __half*)w2f, K2,
            K2, fc_b, out, N2, N2);
    }

    // 5. L2 normalize
    norm_kernel<<<NROWS / 8, 256>>>(out);
}

// round 16
// speedup vs baseline: 2.5502x; 2.5502x over previous
#include <cuda_runtime.h>
#include <cuda_fp16.h>
#include <math.h>
#include <stdint.h>

// ---------------------------------------------------------------- constants
#define NROWS   9216      // B*R
#define K1      2816      // IMG+TAG
#define K2      3072      // padded (3016 -> 3072)
#define K2RAW   3016
#define N1      200       // POS_EMBED
#define N1P     256       // padded
#define N2      1024
#define BOXL    15
#define PEMB    200

#define BK      64        // fp16 K elements per stage (128B per row)

// ---------------------------------------------------------------- scratch
__device__ __half g_Xf[(long)NROWS * K2];
__device__ __half g_W2f[(long)N2 * K2];
__device__ __half g_W1f[(long)N1P * K1];
__device__ float g_region[(long)NROWS * N1];

// ---------------------------------------------------------------- utils
__device__ __forceinline__ uint32_t smem_u32(const void* p) {
    uint32_t a;
    asm("{ .reg .u64 t; cvta.to.shared.u64 t, %1; cvt.u32.u64 %0, t; }"
        : "=r"(a) : "l"(p));
    return a;
}
// SW128 swizzle on 128B rows: chunk(16B) ^= row&7 — conflict-free ldsm/STS
__device__ __forceinline__ uint32_t swz128(uint32_t row, uint32_t chunk) {
    return row * 128 + ((chunk ^ (row & 7)) << 4);
}
__device__ __forceinline__ void cp16(uint32_t dst, const void* src) {
    asm volatile("cp.async.cg.shared.global [%0], [%1], 16;" :: "r"(dst), "l"(src));
}
__device__ __forceinline__ void cp_commit() {
    asm volatile("cp.async.commit_group;" ::: "memory");
}
template<int N>
__device__ __forceinline__ void cp_wait() {
    asm volatile("cp.async.wait_group %0;" :: "n"(N) : "memory");
}
__device__ __forceinline__ void ldsm4(uint32_t* r, uint32_t addr) {
    asm volatile("ldmatrix.sync.aligned.m8n8.x4.shared.b16 {%0,%1,%2,%3}, [%4];"
                 : "=r"(r[0]), "=r"(r[1]), "=r"(r[2]), "=r"(r[3]) : "r"(addr));
}
__device__ __forceinline__ void mma16816(float* d, const uint32_t* a,
                                         uint32_t b0, uint32_t b1) {
    asm volatile(
        "mma.sync.aligned.m16n8k16.row.col.f32.f16.f16.f32 "
        "{%0,%1,%2,%3}, {%4,%5,%6,%7}, {%8,%9}, {%0,%1,%2,%3};"
        : "+f"(d[0]), "+f"(d[1]), "+f"(d[2]), "+f"(d[3])
        : "r"(a[0]), "r"(a[1]), "r"(a[2]), "r"(a[3]), "r"(b0), "r"(b1));
}

// ---------------------------------------------------------------- conversions
__global__ void convX_kernel(const float* __restrict__ images,
                             const float* __restrict__ tag) {
    int i = blockIdx.x * blockDim.x + threadIdx.x;
    if (i >= NROWS * 768) return;
    int row = i / 768;
    int c4  = i - row * 768;
    float4 v;
    if (c4 < 512)      v = reinterpret_cast<const float4*>(images)[(long)row * 512 + c4];
    else if (c4 < 704) v = reinterpret_cast<const float4*>(tag)[(long)row * 192 + (c4 - 512)];
    else if (c4 < 754) return;   // box_feat region: written by attn kernel
    else               v = make_float4(0.f, 0.f, 0.f, 0.f);
    __half h[4];
    h[0] = __float2half_rn(v.x); h[1] = __float2half_rn(v.y);
    h[2] = __float2half_rn(v.z); h[3] = __float2half_rn(v.w);
    *reinterpret_cast<uint2*>(g_Xf + (long)row * K2 + c4 * 4) =
        *reinterpret_cast<uint2*>(h);
}

__global__ void convW2_kernel(const float* __restrict__ fcW) {
    int i = blockIdx.x * blockDim.x + threadIdx.x;
    if (i >= N2 * K2) return;
    int n = i / K2;
    int k = i - n * K2;
    float v;
    if (k < 2048)      v = fcW[(long)n * K2RAW + k];
    else if (k < 2816) v = fcW[(long)n * K2RAW + k + 200];
    else if (k < 3016) v = fcW[(long)n * K2RAW + k - 768];
    else               v = 0.f;
    g_W2f[i] = __float2half_rn(v);
}

__global__ void convW1_kernel(const float* __restrict__ aW) {
    int i = blockIdx.x * blockDim.x + threadIdx.x;
    if (i >= N1P * K1) return;
    int n = i / K1;
    int k = i - n * K1;
    float v = (n < N1) ? aW[(long)n * K1 + k] : 0.f;
    g_W1f[i] = __float2half_rn(v);
}

// ---------------------------------------------------------------- HMMA GEMM (fp16, f32 acc)
// C[M,N] = A[M,K]*B[N,K]^T (+bias). TBM x TBN tile per CTA, MW x NW warp grid,
// NTH threads, NSTG stages, BK=64, SW128-swizzled 128B rows,
// single barrier per K-stage, OCC CTAs/SM. NSKIP: skip padded-N column groups.
template<int TBM, int TBN, int MW, int NW, int NSTG, int NTH, int OCC, bool NSKIP>
__global__ void __launch_bounds__(NTH, OCC)
hmma_gemm(const __half* __restrict__ A, int lda,
          const __half* __restrict__ B, int ldb,
          int K, const float* __restrict__ bias,
          float* __restrict__ C, int N, int ldc) {
    constexpr int MT = (TBM / MW) / 16;
    constexpr int NT = (TBN / NW) / 8;
    constexpr int NP = NT / 2;
    constexpr int T_B = TBM * 128;
    constexpr int STAGE_B = (TBM + TBN) * 128;
    constexpr int GR_A = TBM * 8;
    constexpr int GR_TOT = (TBM + TBN) * 8;
    constexpr int LREP = GR_TOT / NTH;

    extern __shared__ char smem[];
    const uint32_t sb = smem_u32(smem);
    const int tid  = threadIdx.x;
    const int lane = tid & 31;
    const int wid  = tid >> 5;
    const int wm   = (wid % MW) * (TBM / MW);
    const int wn   = (wid / MW) * (TBN / NW);
    const long m0  = (long)blockIdx.y * TBM;
    const long n0  = (long)blockIdx.x * TBN;

    bool np_act[NP];
#pragma unroll
    for (int np = 0; np < NP; np++)
        np_act[np] = NSKIP ? (((int)n0 + wn + np * 16) < N) : true;

    float acc[MT][NT][4];
#pragma unroll
    for (int i = 0; i < MT; i++)
#pragma unroll
        for (int j = 0; j < NT; j++)
#pragma unroll
            for (int c = 0; c < 4; c++) acc[i][j][c] = 0.f;

    uint32_t a_rb[MT], a_rx[MT];
#pragma unroll
    for (int mt = 0; mt < MT; mt++) {
        uint32_t r = wm + mt * 16 + (lane & 15);
        a_rb[mt] = r * 128; a_rx[mt] = r & 7;
    }
    const uint32_t a_cb = lane >> 4;
    uint32_t b_rb[NP], b_rx[NP];
#pragma unroll
    for (int np = 0; np < NP; np++) {
        uint32_t r = wn + np * 16 + ((lane & 7) | ((lane >> 4) << 3));
        b_rb[np] = r * 128; b_rx[np] = r & 7;
    }
    const uint32_t b_cb = (lane >> 3) & 1;

    auto load_stage = [&](int buf, long kel) {
        uint32_t st = sb + buf * STAGE_B;
#pragma unroll
        for (int i = 0; i < LREP; i++) {
            int g = tid + i * NTH;
            int chunk = g & 7;
            if (g < GR_A) {
                int row = g >> 3;
                cp16(st + swz128(row, chunk),
                     A + (m0 + row) * lda + kel + chunk * 8);
            } else {
                int row = (g - GR_A) >> 3;
                cp16(st + T_B + swz128(row, chunk),
                     B + (n0 + row) * ldb + kel + chunk * 8);
            }
        }
    };

    const int S = K / BK;
#pragma unroll 1
    for (int p = 0; p < NSTG - 1; p++) {
        load_stage(p, (long)p * BK);
        cp_commit();
    }

#pragma unroll 1
    for (int s = 0; s < S; s++) {
        cp_wait<NSTG - 2>();
        __syncthreads();
        if (s + NSTG - 1 < S)
            load_stage((s + NSTG - 1) % NSTG, (long)(s + NSTG - 1) * BK);
        cp_commit();

        uint32_t st = sb + (s % NSTG) * STAGE_B;
#pragma unroll
        for (int kk = 0; kk < 4; kk++) {
            uint32_t af[MT][4], bf[NP][4];
            const uint32_t ac = kk * 2 + a_cb;
            const uint32_t bc = kk * 2 + b_cb;
#pragma unroll
            for (int mt = 0; mt < MT; mt++)
                ldsm4(af[mt], st + a_rb[mt] + ((ac ^ a_rx[mt]) << 4));
#pragma unroll
            for (int np = 0; np < NP; np++)
                if (np_act[np])
                    ldsm4(bf[np], st + T_B + b_rb[np] + ((bc ^ b_rx[np]) << 4));
#pragma unroll
            for (int np = 0; np < NP; np++)
                if (np_act[np])
#pragma unroll
                    for (int j = 0; j < 2; j++)
#pragma unroll
                        for (int mt = 0; mt < MT; mt++)
                            mma16816(acc[mt][np * 2 + j], af[mt],
                                     bf[np][2 * j], bf[np][2 * j + 1]);
        }
    }

    // epilogue
    const int gr = lane >> 2;
    const int gc = (lane & 3) * 2;
#pragma unroll
    for (int mt = 0; mt < MT; mt++) {
        long m = m0 + wm + mt * 16 + gr;
#pragma unroll
        for (int nt = 0; nt < NT; nt++) {
            int n = (int)n0 + wn + nt * 8 + gc;
            if (n < N) {
                float b0 = bias ? bias[n] : 0.f;
                float b1 = bias ? bias[n + 1] : 0.f;
                float2 v0 = make_float2(acc[mt][nt][0] + b0, acc[mt][nt][1] + b1);
                float2 v1 = make_float2(acc[mt][nt][2] + b0, acc[mt][nt][3] + b1);
                *reinterpret_cast<float2*>(C + m * ldc + n) = v0;
                *reinterpret_cast<float2*>(C + (m + 8) * ldc + n) = v1;
            }
        }
    }
}

// ---------------------------------------------------------------- attention
// One warp per row, fully static unrolling. idx/w recomputed from L1-hot
// gmem (no register arrays for them) to cut live registers.
__global__ void attn_kernel(const float* __restrict__ boxes,
                            const float* __restrict__ pos_emb) {
    int row  = blockIdx.x * 8 + (threadIdx.x >> 5);
    int lane = threadIdx.x & 31;
    if (row >= NROWS) return;

    const float* region = g_region + (long)row * N1;
    float reg[7];
#pragma unroll
    for (int i = 0; i < 7; i++) {
        int e = lane + 32 * i;
        reg[i] = (e < PEMB) ? region[e] : 0.f;
    }

    const float* brow = boxes + (long)row * (2 * BOXL);
    float sc[BOXL];

#pragma unroll
    for (int k = 0; k < BOXL; k++) {
        const float* pe = pos_emb + (long)((int)brow[k]) * PEMB;
        float p = 0.f;
#pragma unroll
        for (int i = 0; i < 7; i++) {
            int e = lane + 32 * i;
            if (e < PEMB) p += reg[i] * pe[e];
        }
#pragma unroll
        for (int o = 16; o > 0; o >>= 1)
            p += __shfl_xor_sync(0xffffffffu, p, o);
        sc[k] = tanhf(p);
    }

    float mx = -1e30f;
#pragma unroll
    for (int k = 0; k < BOXL; k++) mx = fmaxf(mx, sc[k]);
    float ssum = 0.f;
#pragma unroll
    for (int k = 0; k < BOXL; k++) { sc[k] = expf(sc[k] - mx); ssum += sc[k]; }
    float tot = 0.f;
#pragma unroll
    for (int k = 0; k < BOXL; k++) { sc[k] = sc[k] / ssum * brow[BOXL + k]; tot += sc[k]; }
    float inv = 1.f / (tot + 1e-6f);

#pragma unroll
    for (int i = 0; i < 7; i++) {
        int e = lane + 32 * i;
        if (e < PEMB) {
            float f = 0.f;
#pragma unroll
            for (int k = 0; k < BOXL; k++)
                f += sc[k] * pos_emb[(long)((int)brow[k]) * PEMB + e];
            g_Xf[(long)row * K2 + K1 + e] = __float2half_rn(f * inv);
        }
    }
}

// ---------------------------------------------------------------- L2 norm
__global__ void norm_kernel(float* __restrict__ out) {
    int row  = blockIdx.x * 8 + (threadIdx.x >> 5);
    int lane = threadIdx.x & 31;
    if (row >= NROWS) return;

    float4* p = reinterpret_cast<float4*>(out + (long)row * N2);
    float4 v[8];
    float s = 0.f;
#pragma unroll
    for (int i = 0; i < 8; i++) {
        v[i] = p[lane + 32 * i];
        s += v[i].x * v[i].x + v[i].y * v[i].y + v[i].z * v[i].z + v[i].w * v[i].w;
    }
#pragma unroll
    for (int o = 16; o > 0; o >>= 1)
        s += __shfl_xor_sync(0xffffffffu, s, o);
    float scale = 1.f / (sqrtf(s) + 1e-8f);
#pragma unroll
    for (int i = 0; i < 8; i++) {
        v[i].x *= scale; v[i].y *= scale; v[i].z *= scale; v[i].w *= scale;
        p[lane + 32 * i] = v[i];
    }
}

// ---------------------------------------------------------------- launch
#define SMEM1 (4 * (64 + 128) * 128)    //  98304 — GEMM1 (TBM=64, 4 stg, 2 CTA/SM)
#define SMEM2 (3 * (128 + 128) * 128)   //  98304 — GEMM2 (TBM=128, 3 stg, 2 CTA/SM)

extern "C" void kernel_launch(void* const* d_in, const int* in_sizes, int n_in,
                              void* d_out, int out_size) {
    const float* images  = (const float*)d_in[0];
    const float* tag     = (const float*)d_in[1];
    const float* boxes   = (const float*)d_in[2];
    const float* pos_emb = (const float*)d_in[3];
    const float* attn_W  = (const float*)d_in[4];
    const float* fc_W    = (const float*)d_in[5];
    const float* fc_b    = (const float*)d_in[6];
    float* out = (float*)d_out;

    cudaFuncSetAttribute(hmma_gemm<64, 128, 2, 2, 4, 128, 2, true>,
                         cudaFuncAttributeMaxDynamicSharedMemorySize, SMEM1);
    cudaFuncSetAttribute(hmma_gemm<128, 128, 2, 2, 3, 128, 2, false>,
                         cudaFuncAttributeMaxDynamicSharedMemorySize, SMEM2);

    void *xf, *w2f, *w1f, *rg;
    cudaGetSymbolAddress(&xf, g_Xf);
    cudaGetSymbolAddress(&w2f, g_W2f);
    cudaGetSymbolAddress(&w1f, g_W1f);
    cudaGetSymbolAddress(&rg, g_region);

    // 1. conversions (fp16)
    convX_kernel<<<(NROWS * 768 + 255) / 256, 256>>>(images, tag);
    convW2_kernel<<<(N2 * K2 + 255) / 256, 256>>>(fc_W);
    convW1_kernel<<<(N1P * K1 + 255) / 256, 256>>>(attn_W);

    // 2. GEMM1: region = X[:, :2816] @ attn_W^T
    //    288 CTAs, TBM=64, 2 CTA/SM, N-skip on padded cols (measured 39.4us)
    {
        dim3 grid(N1P / 128, NROWS / 64);
        hmma_gemm<64, 128, 2, 2, 4, 128, 2, true><<<grid, 128, SMEM1>>>(
            (const __half*)xf, K2, (const __half*)w1f, K1,
            K1, nullptr, (float*)rg, N1, N1);
    }

    // 3. attention -> box_feat (fp16) into X[:, 2816:3016]
    attn_kernel<<<NROWS / 8, 256>>>(boxes, pos_emb);

    // 4. GEMM2: out = X @ W2^T + fc_b  (R12 proven config: 576 CTAs, 2 CTA/SM)
    {
        dim3 grid(N2 / 128, NROWS / 128);
        hmma_gemm<128, 128, 2, 2, 3, 128, 2, false><<<grid, 128, SMEM2>>>(
            (const __half*)xf, K2, (const __half*)w2f, K2,
            K2, fc_b, out, N2, N2);
    }

    // 5. L2 normalize
    norm_kernel<<<NROWS / 8, 256>>>(out);
}